// round 14
// baseline (speedup 1.0000x reference)
#include <cuda_runtime.h>

#define C16  16
#define GH32 32
#define W512 512
#define HW   (512 * 512)

// Constant bank, R8-dense layout (NOT duplicated — R13 proved dup'd is worse).
// 0.125 (the 8-neighbor mean) is folded into W2 and MW, so sv = raw sums.
#define OFF_W1 0        // [c][j]  16*32
#define OFF_W2 512      // [c][j]  16*32  (= 0.125 * g1w[:,16:] @ mw)
#define OFF_G2 1024     // [gp][j][e]  8*32*2 (= g2w[2gp+e][j])
#define OFF_MW 1536     // [c][d]  16*16  (= 0.125 * mw[d][c])
#define OFF_B1 1792     // 32            (= g1b + g1w[:,16:] @ mb)
#define OFF_GB 1824     // 16            (g2b)
#define OFF_MB 1840     // 16            (mb)
#define NWC    1856

__constant__ __align__(16) float cwts[NWC];
__device__   __align__(16) float g_wbuf[NWC];

// Packed f32x2 ops (Blackwell sm_103a).
__device__ __forceinline__ float2 ffma2(float2 a, float2 b, float2 c) {
    float2 d;
    asm("fma.rn.f32x2 %0, %1, %2, %3;"
        : "=l"(reinterpret_cast<unsigned long long&>(d))
        : "l"(reinterpret_cast<unsigned long long&>(a)),
          "l"(reinterpret_cast<unsigned long long&>(b)),
          "l"(reinterpret_cast<unsigned long long&>(c)));
    return d;
}
__device__ __forceinline__ float2 fadd2(float2 a, float2 b) {
    float2 d;
    asm("add.rn.f32x2 %0, %1, %2;"
        : "=l"(reinterpret_cast<unsigned long long&>(d))
        : "l"(reinterpret_cast<unsigned long long&>(a)),
          "l"(reinterpret_cast<unsigned long long&>(b)));
    return d;
}
__device__ __forceinline__ float2 dup2(float v) { return make_float2(v, v); }
__device__ __forceinline__ float4 ldc4(int idx) {
    return *reinterpret_cast<const float4*>(&cwts[idx]);
}
__device__ __forceinline__ float2 ldc2(int idx) {
    return *reinterpret_cast<const float2*>(&cwts[idx]);
}

// ---- prep: fold weights (incl. the 0.125 mean factor) into constant bank ----
__global__ void prep_weights(const float* __restrict__ mw,  const float* __restrict__ mb,
                             const float* __restrict__ g1w, const float* __restrict__ g1b,
                             const float* __restrict__ g2w, const float* __restrict__ g2b)
{
    const int t = threadIdx.x;
    for (int i = t; i < C16 * GH32; i += 256) {
        int c = i >> 5, j = i & 31;
        g_wbuf[OFF_W1 + i] = g1w[j * (2 * C16) + c];
        float acc = 0.f;
        #pragma unroll
        for (int k = 0; k < C16; k++)
            acc += g1w[j * (2 * C16) + C16 + k] * mw[k * C16 + c];
        g_wbuf[OFF_W2 + i] = acc * 0.125f;       // mean factor folded
    }
    for (int i = t; i < 8 * GH32 * 2; i += 256) {
        int gp = i >> 6, r = i & 63, j = r >> 1, e = r & 1;
        g_wbuf[OFF_G2 + i] = g2w[(2 * gp + e) * GH32 + j];
    }
    if (t < 256) {
        int c = t >> 4, d = t & 15;
        g_wbuf[OFF_MW + t] = mw[d * C16 + c] * 0.125f;  // mean factor folded
    }
    if (t < GH32) {
        float acc = g1b[t];
        #pragma unroll
        for (int k = 0; k < C16; k++)
            acc += g1w[t * (2 * C16) + C16 + k] * mb[k];
        g_wbuf[OFF_B1 + t] = acc;
    }
    if (t >= 32 && t < 32 + C16) g_wbuf[OFF_MB + t - 32] = mb[t - 32];
    if (t >= 64 && t < 64 + C16) g_wbuf[OFF_GB + t - 64] = g2b[t - 64];
}

// Identity: softmax over 8 identical affinities = 1/8 each, so with
// sv = RAW 8-neighbor sum (0.125 folded into W2/MW):
//   agg    = MW' @ sv + mb
//   hidden = relu(W1 @ x + W2' @ sv + b1')
//   out    = agg * sigmoid(g2w @ hidden + g2b)
//
// The R8 instruction mix (2 px/thread, output-channel f32x2 pairs, dense
// const-bank weights) at 24 warps/SM: sv lives in smem (frees 32 regs; the
// phase-2 live set gacc32+hreg16+temps fits the 85-reg cap of occ-3), and
// blocks are 32x16 PIXEL TILES so the gather halo (61 KB/block, 27 MB
// chip-wide) respects both the L1D carveout (228-96=132 KB) and L2 — fixing
// R6's geometry failure while keeping R10/R12's spill trap avoided by
// deliberately placing sv in smem instead of letting ptxas spill it.
__global__ __launch_bounds__(256, 3) void fused_graphaug_kernel(
    const float* __restrict__ x,
    float* __restrict__ out)
{
    // Per-thread sv: [c][t] float2, lane-stride 8B -> conflict-free LDS.64.
    __shared__ __align__(16) float sSV[C16 * 256 * 2];   // 32 KB

    const int t = threadIdx.x;

    // ---- 2D tile indexing: 32x16 px tile = 256 threads x 2 px ----
    // blockIdx: [b(2) | tileY(5, 32 tiles of 16 rows) | tileX(4, 16 tiles of 32 cols)]
    const int b     = blockIdx.x >> 9;
    const int rem   = blockIdx.x & 511;
    const int tileY = rem >> 4;
    const int tileX = rem & 15;
    const int tx = t & 15;                       // col-pair 0..15
    const int ty = t >> 4;                       // row 0..15
    const int w0 = tileX * 32 + tx * 2;          // even column
    const int h  = tileY * 16 + ty;

    const float* xb    = x + (size_t)b * C16 * HW;
    const int    center = h * W512 + w0;

    // ---- sv = raw sum of 8 rolls per channel -> smem ----
    {
        constexpr int DY[8] = {-4, -4, -4, -3, -2, 2, 3, 4};
        constexpr int DX[8] = {-4, -1,  2,  4, -3, 3, -2, 4};
        int roff[8], cb[8];
        #pragma unroll
        for (int i = 0; i < 8; i++) {
            roff[i] = ((h - DY[i]) & (W512 - 1)) * W512;
            cb[i]   = (w0 - DX[i]) & (W512 - 1);
        }
        #pragma unroll
        for (int c = 0; c < C16; c++) {
            const float* xp = xb + c * HW;
            float2 acc = make_float2(0.f, 0.f);
            #pragma unroll
            for (int i = 0; i < 8; i++) {
                float2 v;
                if ((DX[i] & 1) == 0) {
                    // even dx: cb even <= 510 -> aligned contiguous float2
                    v = *reinterpret_cast<const float2*>(xp + roff[i] + cb[i]);
                } else {
                    v.x = __ldg(xp + roff[i] + cb[i]);
                    v.y = __ldg(xp + roff[i] + ((cb[i] + 1) & (W512 - 1)));
                }
                acc = fadd2(acc, v);
            }
            // same-thread RAW through smem: no barrier needed
            *reinterpret_cast<float2*>(&sSV[(c * 256 + t) * 2]) = acc;
        }
    }

    // ---- gate accumulators: gacc[gp][px] packs outputs (2gp, 2gp+1) ----
    float2 gacc[8][2];
    #pragma unroll
    for (int gp = 0; gp < 8; gp++) {
        float2 gb = ldc2(OFF_GB + 2 * gp);
        gacc[gp][0] = gb; gacc[gp][1] = gb;
    }

    // ---- hidden in 4 chunks of 8 units, W1/W2 merged per c (hreg = 16 regs) ----
    #pragma unroll
    for (int jt = 0; jt < 4; jt++) {
        const int j0 = jt * 8;
        float2 hreg[4][2];                       // pairs (j0+2l, j0+2l+1) x 2 px
        #pragma unroll
        for (int jl = 0; jl < 4; jl++) {
            float2 bv = ldc2(OFF_B1 + j0 + 2 * jl);
            hreg[jl][0] = bv; hreg[jl][1] = bv;
        }
        #pragma unroll
        for (int c = 0; c < C16; c++) {
            float2 xc = *reinterpret_cast<const float2*>(xb + c * HW + center);
            float2 sc = *reinterpret_cast<const float2*>(&sSV[(c * 256 + t) * 2]);
            float2 xd0 = dup2(xc.x), xd1 = dup2(xc.y);
            float2 sd0 = dup2(sc.x), sd1 = dup2(sc.y);
            float4 wa = ldc4(OFF_W1 + c * GH32 + j0);
            float4 wb = ldc4(OFF_W1 + c * GH32 + j0 + 4);
            float4 va = ldc4(OFF_W2 + c * GH32 + j0);
            float4 vb = ldc4(OFF_W2 + c * GH32 + j0 + 4);
            hreg[0][0] = ffma2(make_float2(wa.x, wa.y), xd0, hreg[0][0]);
            hreg[0][1] = ffma2(make_float2(wa.x, wa.y), xd1, hreg[0][1]);
            hreg[1][0] = ffma2(make_float2(wa.z, wa.w), xd0, hreg[1][0]);
            hreg[1][1] = ffma2(make_float2(wa.z, wa.w), xd1, hreg[1][1]);
            hreg[2][0] = ffma2(make_float2(wb.x, wb.y), xd0, hreg[2][0]);
            hreg[2][1] = ffma2(make_float2(wb.x, wb.y), xd1, hreg[2][1]);
            hreg[3][0] = ffma2(make_float2(wb.z, wb.w), xd0, hreg[3][0]);
            hreg[3][1] = ffma2(make_float2(wb.z, wb.w), xd1, hreg[3][1]);
            hreg[0][0] = ffma2(make_float2(va.x, va.y), sd0, hreg[0][0]);
            hreg[0][1] = ffma2(make_float2(va.x, va.y), sd1, hreg[0][1]);
            hreg[1][0] = ffma2(make_float2(va.z, va.w), sd0, hreg[1][0]);
            hreg[1][1] = ffma2(make_float2(va.z, va.w), sd1, hreg[1][1]);
            hreg[2][0] = ffma2(make_float2(vb.x, vb.y), sd0, hreg[2][0]);
            hreg[2][1] = ffma2(make_float2(vb.x, vb.y), sd1, hreg[2][1]);
            hreg[3][0] = ffma2(make_float2(vb.z, vb.w), sd0, hreg[3][0]);
            hreg[3][1] = ffma2(make_float2(vb.z, vb.w), sd1, hreg[3][1]);
        }
        // relu
        #pragma unroll
        for (int jl = 0; jl < 4; jl++) {
            hreg[jl][0].x = fmaxf(hreg[jl][0].x, 0.f);
            hreg[jl][0].y = fmaxf(hreg[jl][0].y, 0.f);
            hreg[jl][1].x = fmaxf(hreg[jl][1].x, 0.f);
            hreg[jl][1].y = fmaxf(hreg[jl][1].y, 0.f);
        }
        // gate accumulation
        #pragma unroll
        for (int jl = 0; jl < 4; jl++) {
            const int jg = j0 + 2 * jl;
            float2 ha0 = dup2(hreg[jl][0].x), hb0 = dup2(hreg[jl][0].y);
            float2 ha1 = dup2(hreg[jl][1].x), hb1 = dup2(hreg[jl][1].y);
            #pragma unroll
            for (int gp = 0; gp < 8; gp++) {
                float4 wq = ldc4(OFF_G2 + gp * 64 + jg * 2);
                gacc[gp][0] = ffma2(make_float2(wq.x, wq.y), ha0, gacc[gp][0]);
                gacc[gp][0] = ffma2(make_float2(wq.z, wq.w), hb0, gacc[gp][0]);
                gacc[gp][1] = ffma2(make_float2(wq.x, wq.y), ha1, gacc[gp][1]);
                gacc[gp][1] = ffma2(make_float2(wq.z, wq.w), hb1, gacc[gp][1]);
            }
        }
    }

    // ---- agg = MW' @ sv + mb, two d-pairs at a time, fused epilogue ----
    float* ob = out + (size_t)b * C16 * HW + center;
    #pragma unroll
    for (int dp = 0; dp < 8; dp += 2) {
        float2 mv0 = ldc2(OFF_MB + 2 * dp);
        float2 mv1 = ldc2(OFF_MB + 2 * dp + 2);
        float2 a00 = mv0, a01 = mv0;     // pair (2dp,2dp+1)   @ px0 / px1
        float2 a10 = mv1, a11 = mv1;     // pair (2dp+2,2dp+3) @ px0 / px1
        #pragma unroll
        for (int c = 0; c < C16; c++) {
            float2 sc = *reinterpret_cast<const float2*>(&sSV[(c * 256 + t) * 2]);
            float2 sd0 = dup2(sc.x), sd1 = dup2(sc.y);
            float4 wq = ldc4(OFF_MW + c * C16 + dp * 2);
            a00 = ffma2(make_float2(wq.x, wq.y), sd0, a00);
            a01 = ffma2(make_float2(wq.x, wq.y), sd1, a01);
            a10 = ffma2(make_float2(wq.z, wq.w), sd0, a10);
            a11 = ffma2(make_float2(wq.z, wq.w), sd1, a11);
        }
        #pragma unroll
        for (int e = 0; e < 2; e++) {
            float2 v0 = e ? a10 : a00;           // px0: (d, d+1)
            float2 v1 = e ? a11 : a01;           // px1: (d, d+1)
            const int d0 = 2 * (dp + e);
            float g00 = 1.f / (1.f + __expf(-gacc[dp + e][0].x));
            float g01 = 1.f / (1.f + __expf(-gacc[dp + e][1].x));
            float g10 = 1.f / (1.f + __expf(-gacc[dp + e][0].y));
            float g11 = 1.f / (1.f + __expf(-gacc[dp + e][1].y));
            *reinterpret_cast<float2*>(ob + (size_t)d0 * HW) =
                make_float2(v0.x * g00, v1.x * g01);
            *reinterpret_cast<float2*>(ob + (size_t)(d0 + 1) * HW) =
                make_float2(v0.y * g10, v1.y * g11);
        }
    }
}

extern "C" void kernel_launch(void* const* d_in, const int* in_sizes, int n_in,
                              void* d_out, int out_size) {
    // metadata order: x, qw, qb, kw, kb, mw, mb, scaling, g1w, g1b, g2w, g2b
    const float* x   = (const float*)d_in[0];
    const float* mw  = (const float*)d_in[5];
    const float* mb  = (const float*)d_in[6];
    const float* g1w = (const float*)d_in[8];
    const float* g1b = (const float*)d_in[9];
    const float* g2w = (const float*)d_in[10];
    const float* g2b = (const float*)d_in[11];
    float* out = (float*)d_out;

    prep_weights<<<1, 256>>>(mw, mb, g1w, g1b, g2w, g2b);

    void* wsrc = nullptr;
    cudaGetSymbolAddress(&wsrc, g_wbuf);
    cudaMemcpyToSymbolAsync(cwts, wsrc, NWC * sizeof(float), 0,
                            cudaMemcpyDeviceToDevice, 0);

    // 4 batches x (32 y-tiles x 16 x-tiles) = 2048 blocks; 256 thr x 2 px = 32x16 tile
    fused_graphaug_kernel<<<2048, 256>>>(x, out);
}

// round 15
// speedup vs baseline: 2.1068x; 2.1068x over previous
#include <cuda_runtime.h>

#define C16  16
#define GH32 32
#define W512 512
#define HW   (512 * 512)

// Constant bank, R8-dense layout. 0.125 (the 8-neighbor mean) is folded into
// W2 and MW at prep time, so sv can stay as the RAW 8-neighbor sum.
#define OFF_W1 0        // [c][j]  16*32
#define OFF_W2 512      // [c][j]  16*32  (= 0.125 * g1w[:,16:] @ mw)
#define OFF_G2 1024     // [gp][j][e]  8*32*2 (= g2w[2gp+e][j])
#define OFF_MW 1536     // [c][d]  16*16  (= 0.125 * mw[d][c])
#define OFF_B1 1792     // 32            (= g1b + g1w[:,16:] @ mb)
#define OFF_GB 1824     // 16            (g2b)
#define OFF_MB 1840     // 16            (mb)
#define NWC    1856

__constant__ __align__(16) float cwts[NWC];
__device__   __align__(16) float g_wbuf[NWC];

// Packed f32x2 ops (Blackwell sm_103a).
__device__ __forceinline__ float2 ffma2(float2 a, float2 b, float2 c) {
    float2 d;
    asm("fma.rn.f32x2 %0, %1, %2, %3;"
        : "=l"(reinterpret_cast<unsigned long long&>(d))
        : "l"(reinterpret_cast<unsigned long long&>(a)),
          "l"(reinterpret_cast<unsigned long long&>(b)),
          "l"(reinterpret_cast<unsigned long long&>(c)));
    return d;
}
__device__ __forceinline__ float2 fadd2(float2 a, float2 b) {
    float2 d;
    asm("add.rn.f32x2 %0, %1, %2;"
        : "=l"(reinterpret_cast<unsigned long long&>(d))
        : "l"(reinterpret_cast<unsigned long long&>(a)),
          "l"(reinterpret_cast<unsigned long long&>(b)));
    return d;
}
__device__ __forceinline__ float2 dup2(float v) { return make_float2(v, v); }
__device__ __forceinline__ float4 ldc4(int idx) {
    return *reinterpret_cast<const float4*>(&cwts[idx]);
}
__device__ __forceinline__ float2 ldc2(int idx) {
    return *reinterpret_cast<const float2*>(&cwts[idx]);
}

// ---- prep: fold weights (incl. the 0.125 mean factor) into constant bank ----
__global__ void prep_weights(const float* __restrict__ mw,  const float* __restrict__ mb,
                             const float* __restrict__ g1w, const float* __restrict__ g1b,
                             const float* __restrict__ g2w, const float* __restrict__ g2b)
{
    const int t = threadIdx.x;
    for (int i = t; i < C16 * GH32; i += 256) {
        int c = i >> 5, j = i & 31;
        g_wbuf[OFF_W1 + i] = g1w[j * (2 * C16) + c];
        float acc = 0.f;
        #pragma unroll
        for (int k = 0; k < C16; k++)
            acc += g1w[j * (2 * C16) + C16 + k] * mw[k * C16 + c];
        g_wbuf[OFF_W2 + i] = acc * 0.125f;       // mean factor folded
    }
    for (int i = t; i < 8 * GH32 * 2; i += 256) {
        int gp = i >> 6, r = i & 63, j = r >> 1, e = r & 1;
        g_wbuf[OFF_G2 + i] = g2w[(2 * gp + e) * GH32 + j];
    }
    if (t < 256) {
        int c = t >> 4, d = t & 15;
        g_wbuf[OFF_MW + t] = mw[d * C16 + c] * 0.125f;  // mean factor folded
    }
    if (t < GH32) {
        float acc = g1b[t];
        #pragma unroll
        for (int k = 0; k < C16; k++)
            acc += g1w[t * (2 * C16) + C16 + k] * mb[k];
        g_wbuf[OFF_B1 + t] = acc;
    }
    if (t >= 32 && t < 32 + C16) g_wbuf[OFF_MB + t - 32] = mb[t - 32];
    if (t >= 64 && t < 64 + C16) g_wbuf[OFF_GB + t - 64] = g2b[t - 64];
}

// Identity: softmax over 8 identical affinities = 1/8 each, so with
// sv = RAW 8-neighbor sum (0.125 folded into W2/MW):
//   agg    = MW' @ sv + mb
//   hidden = relu(W1 @ x + W2' @ sv + b1')
//   out    = agg * sigmoid(g2w @ hidden + g2b)
//
// EXACT R8 shape — the empirically best configuration (2 px/thread,
// output-channel f32x2 pairs, dense const-bank weights, 256 thr, occ-2,
// 128 regs, zero smem). Five rounds of occupancy experiments all spilled or
// thrashed; the ~116-reg live set makes 16 warps/SM the stable optimum.
__global__ __launch_bounds__(256, 2) void fused_graphaug_kernel(
    const float* __restrict__ x,
    float* __restrict__ out)
{
    const int t = threadIdx.x;

    // ---- Pixel-pair indexing (2 horizontally-adjacent pixels per thread) ----
    const int tidg = blockIdx.x * 256 + t;
    const int p0   = tidg * 2;
    const int w0   = p0 & (W512 - 1);            // even column
    const int h    = (p0 >> 9) & (W512 - 1);
    const int b    = p0 >> 18;

    const float* xb    = x + (size_t)b * C16 * HW;
    const int    center = h * W512 + w0;

    // ---- sv = raw sum of 8 rolls per channel (7 packed adds, init = first) ----
    float2 sv[C16];
    {
        constexpr int DY[8] = {-4, -4, -4, -3, -2, 2, 3, 4};
        constexpr int DX[8] = {-4, -1,  2,  4, -3, 3, -2, 4};
        int roff[8], cb[8];
        #pragma unroll
        for (int i = 0; i < 8; i++) {
            roff[i] = ((h - DY[i]) & (W512 - 1)) * W512;
            cb[i]   = (w0 - DX[i]) & (W512 - 1);
        }
        #pragma unroll
        for (int c = 0; c < C16; c++) {
            const float* xp = xb + c * HW;
            // i=0 has even dx -> aligned float2; use it as the initializer
            float2 acc = *reinterpret_cast<const float2*>(xp + roff[0] + cb[0]);
            #pragma unroll
            for (int i = 1; i < 8; i++) {
                float2 v;
                if ((DX[i] & 1) == 0) {
                    // even dx: cb even <= 510 -> aligned contiguous float2
                    v = *reinterpret_cast<const float2*>(xp + roff[i] + cb[i]);
                } else {
                    v.x = __ldg(xp + roff[i] + cb[i]);
                    v.y = __ldg(xp + roff[i] + ((cb[i] + 1) & (W512 - 1)));
                }
                acc = fadd2(acc, v);
            }
            sv[c] = acc;                          // raw sum; 0.125 is in W2'/MW'
        }
    }

    // ---- gate accumulators: gacc[gp][px] packs outputs (2gp, 2gp+1) ----
    float2 gacc[8][2];
    #pragma unroll
    for (int gp = 0; gp < 8; gp++) {
        float2 gb = ldc2(OFF_GB + 2 * gp);
        gacc[gp][0] = gb; gacc[gp][1] = gb;
    }

    // ---- hidden in 2 chunks of 16 units (8 j-pairs each) ----
    #pragma unroll
    for (int jt = 0; jt < 2; jt++) {
        const int j0 = jt * 16;
        float2 hreg[8][2];                       // pairs (j0+2l, j0+2l+1) x 2 px
        #pragma unroll
        for (int jl = 0; jl < 8; jl++) {
            float2 bv = ldc2(OFF_B1 + j0 + 2 * jl);
            hreg[jl][0] = bv; hreg[jl][1] = bv;
        }
        // W1 @ x (const port; x center loaded once per chunk, L1-resident)
        #pragma unroll
        for (int c = 0; c < C16; c++) {
            float2 xc = *reinterpret_cast<const float2*>(xb + c * HW + center);
            float2 xd0 = dup2(xc.x), xd1 = dup2(xc.y);
            #pragma unroll
            for (int q = 0; q < 4; q++) {        // 4 ldc4 cover 16 units
                float4 wq = ldc4(OFF_W1 + c * GH32 + j0 + 4 * q);
                hreg[2*q][0]   = ffma2(make_float2(wq.x, wq.y), xd0, hreg[2*q][0]);
                hreg[2*q][1]   = ffma2(make_float2(wq.x, wq.y), xd1, hreg[2*q][1]);
                hreg[2*q+1][0] = ffma2(make_float2(wq.z, wq.w), xd0, hreg[2*q+1][0]);
                hreg[2*q+1][1] = ffma2(make_float2(wq.z, wq.w), xd1, hreg[2*q+1][1]);
            }
        }
        // W2' @ sv (const port; sv in registers)
        #pragma unroll
        for (int c = 0; c < C16; c++) {
            float2 sd0 = dup2(sv[c].x), sd1 = dup2(sv[c].y);
            #pragma unroll
            for (int q = 0; q < 4; q++) {
                float4 wq = ldc4(OFF_W2 + c * GH32 + j0 + 4 * q);
                hreg[2*q][0]   = ffma2(make_float2(wq.x, wq.y), sd0, hreg[2*q][0]);
                hreg[2*q][1]   = ffma2(make_float2(wq.x, wq.y), sd1, hreg[2*q][1]);
                hreg[2*q+1][0] = ffma2(make_float2(wq.z, wq.w), sd0, hreg[2*q+1][0]);
                hreg[2*q+1][1] = ffma2(make_float2(wq.z, wq.w), sd1, hreg[2*q+1][1]);
            }
        }
        // relu
        #pragma unroll
        for (int jl = 0; jl < 8; jl++) {
            hreg[jl][0].x = fmaxf(hreg[jl][0].x, 0.f);
            hreg[jl][0].y = fmaxf(hreg[jl][0].y, 0.f);
            hreg[jl][1].x = fmaxf(hreg[jl][1].x, 0.f);
            hreg[jl][1].y = fmaxf(hreg[jl][1].y, 0.f);
        }
        // gate accumulation (const port)
        #pragma unroll
        for (int jl = 0; jl < 8; jl++) {
            const int jg = j0 + 2 * jl;
            float2 ha0 = dup2(hreg[jl][0].x), hb0 = dup2(hreg[jl][0].y);
            float2 ha1 = dup2(hreg[jl][1].x), hb1 = dup2(hreg[jl][1].y);
            #pragma unroll
            for (int gp = 0; gp < 8; gp++) {
                float4 wq = ldc4(OFF_G2 + gp * 64 + jg * 2);
                gacc[gp][0] = ffma2(make_float2(wq.x, wq.y), ha0, gacc[gp][0]);
                gacc[gp][0] = ffma2(make_float2(wq.z, wq.w), hb0, gacc[gp][0]);
                gacc[gp][1] = ffma2(make_float2(wq.x, wq.y), ha1, gacc[gp][1]);
                gacc[gp][1] = ffma2(make_float2(wq.z, wq.w), hb1, gacc[gp][1]);
            }
        }
    }

    // ---- agg = MW' @ sv + mb, two d-pairs at a time, fused epilogue ----
    float* ob = out + (size_t)b * C16 * HW + center;
    #pragma unroll
    for (int dp = 0; dp < 8; dp += 2) {
        float2 mv0 = ldc2(OFF_MB + 2 * dp);
        float2 mv1 = ldc2(OFF_MB + 2 * dp + 2);
        float2 a00 = mv0, a01 = mv0;     // pair (2dp,2dp+1)   @ px0 / px1
        float2 a10 = mv1, a11 = mv1;     // pair (2dp+2,2dp+3) @ px0 / px1
        #pragma unroll
        for (int c = 0; c < C16; c++) {
            float2 sd0 = dup2(sv[c].x), sd1 = dup2(sv[c].y);
            float4 wq = ldc4(OFF_MW + c * C16 + dp * 2);
            a00 = ffma2(make_float2(wq.x, wq.y), sd0, a00);
            a01 = ffma2(make_float2(wq.x, wq.y), sd1, a01);
            a10 = ffma2(make_float2(wq.z, wq.w), sd0, a10);
            a11 = ffma2(make_float2(wq.z, wq.w), sd1, a11);
        }
        #pragma unroll
        for (int e = 0; e < 2; e++) {
            float2 v0 = e ? a10 : a00;           // px0: (d, d+1)
            float2 v1 = e ? a11 : a01;           // px1: (d, d+1)
            const int d0 = 2 * (dp + e);
            float g00 = 1.f / (1.f + __expf(-gacc[dp + e][0].x));
            float g01 = 1.f / (1.f + __expf(-gacc[dp + e][1].x));
            float g10 = 1.f / (1.f + __expf(-gacc[dp + e][0].y));
            float g11 = 1.f / (1.f + __expf(-gacc[dp + e][1].y));
            *reinterpret_cast<float2*>(ob + (size_t)d0 * HW) =
                make_float2(v0.x * g00, v1.x * g01);
            *reinterpret_cast<float2*>(ob + (size_t)(d0 + 1) * HW) =
                make_float2(v0.y * g10, v1.y * g11);
        }
    }
}

extern "C" void kernel_launch(void* const* d_in, const int* in_sizes, int n_in,
                              void* d_out, int out_size) {
    // metadata order: x, qw, qb, kw, kb, mw, mb, scaling, g1w, g1b, g2w, g2b
    const float* x   = (const float*)d_in[0];
    const float* mw  = (const float*)d_in[5];
    const float* mb  = (const float*)d_in[6];
    const float* g1w = (const float*)d_in[8];
    const float* g1b = (const float*)d_in[9];
    const float* g2w = (const float*)d_in[10];
    const float* g2b = (const float*)d_in[11];
    float* out = (float*)d_out;

    prep_weights<<<1, 256>>>(mw, mb, g1w, g1b, g2w, g2b);

    void* wsrc = nullptr;
    cudaGetSymbolAddress(&wsrc, g_wbuf);
    cudaMemcpyToSymbolAsync(cwts, wsrc, NWC * sizeof(float), 0,
                            cudaMemcpyDeviceToDevice, 0);

    // 1,048,576 px -> 524,288 horizontal pairs -> 2048 blocks x 256 threads
    fused_graphaug_kernel<<<2048, 256>>>(x, out);
}

// round 16
// speedup vs baseline: 2.1376x; 1.0146x over previous
#include <cuda_runtime.h>

#define C16  16
#define GH32 32
#define W512 512
#define HW   (512 * 512)

// Constant bank, R8-dense layout. 0.125 (the 8-neighbor mean) is folded into
// W2 and MW at prep time, so sv stays the RAW 8-neighbor sum.
#define OFF_W1 0        // [c][j]  16*32
#define OFF_W2 512      // [c][j]  16*32  (= 0.125 * g1w[:,16:] @ mw)
#define OFF_G2 1024     // [gp][j][e]  8*32*2 (= g2w[2gp+e][j])
#define OFF_MW 1536     // [c][d]  16*16  (= 0.125 * mw[d][c])
#define OFF_B1 1792     // 32            (= g1b + g1w[:,16:] @ mb)
#define OFF_GB 1824     // 16            (g2b)
#define OFF_MB 1840     // 16            (mb)
#define NWC    1856

__constant__ __align__(16) float cwts[NWC];
__device__   __align__(16) float g_wbuf[NWC];

// Packed f32x2 ops (Blackwell sm_103a).
__device__ __forceinline__ float2 ffma2(float2 a, float2 b, float2 c) {
    float2 d;
    asm("fma.rn.f32x2 %0, %1, %2, %3;"
        : "=l"(reinterpret_cast<unsigned long long&>(d))
        : "l"(reinterpret_cast<unsigned long long&>(a)),
          "l"(reinterpret_cast<unsigned long long&>(b)),
          "l"(reinterpret_cast<unsigned long long&>(c)));
    return d;
}
__device__ __forceinline__ float2 fadd2(float2 a, float2 b) {
    float2 d;
    asm("add.rn.f32x2 %0, %1, %2;"
        : "=l"(reinterpret_cast<unsigned long long&>(d))
        : "l"(reinterpret_cast<unsigned long long&>(a)),
          "l"(reinterpret_cast<unsigned long long&>(b)));
    return d;
}
__device__ __forceinline__ float2 dup2(float v) { return make_float2(v, v); }
__device__ __forceinline__ float4 ldc4(int idx) {
    return *reinterpret_cast<const float4*>(&cwts[idx]);
}
__device__ __forceinline__ float2 ldc2(int idx) {
    return *reinterpret_cast<const float2*>(&cwts[idx]);
}

// ---- prep: fold weights (incl. the 0.125 mean factor) into constant bank ----
__global__ void prep_weights(const float* __restrict__ mw,  const float* __restrict__ mb,
                             const float* __restrict__ g1w, const float* __restrict__ g1b,
                             const float* __restrict__ g2w, const float* __restrict__ g2b)
{
    const int t = threadIdx.x;
    for (int i = t; i < C16 * GH32; i += 256) {
        int c = i >> 5, j = i & 31;
        g_wbuf[OFF_W1 + i] = g1w[j * (2 * C16) + c];
        float acc = 0.f;
        #pragma unroll
        for (int k = 0; k < C16; k++)
            acc += g1w[j * (2 * C16) + C16 + k] * mw[k * C16 + c];
        g_wbuf[OFF_W2 + i] = acc * 0.125f;       // mean factor folded
    }
    for (int i = t; i < 8 * GH32 * 2; i += 256) {
        int gp = i >> 6, r = i & 63, j = r >> 1, e = r & 1;
        g_wbuf[OFF_G2 + i] = g2w[(2 * gp + e) * GH32 + j];
    }
    if (t < 256) {
        int c = t >> 4, d = t & 15;
        g_wbuf[OFF_MW + t] = mw[d * C16 + c] * 0.125f;  // mean factor folded
    }
    if (t < GH32) {
        float acc = g1b[t];
        #pragma unroll
        for (int k = 0; k < C16; k++)
            acc += g1w[t * (2 * C16) + C16 + k] * mb[k];
        g_wbuf[OFF_B1 + t] = acc;
    }
    if (t >= 32 && t < 32 + C16) g_wbuf[OFF_MB + t - 32] = mb[t - 32];
    if (t >= 64 && t < 64 + C16) g_wbuf[OFF_GB + t - 64] = g2b[t - 64];
}

// Identity: softmax over 8 identical affinities = 1/8 each, so with
// sv = RAW 8-neighbor sum (0.125 folded into W2/MW):
//   agg    = MW' @ sv + mb
//   hidden = relu(W1 @ x + W2' @ sv + b1')
//   out    = agg * sigmoid(g2w @ hidden + g2b)
//
// R8/R15 shape — the empirically optimal configuration (2 px/thread,
// output-channel f32x2 pairs, dense const-bank weights, 256 thr, occ-2,
// 128 regs, zero smem). This round: the epilogue runs c-OUTER with all 16
// agg accumulators live, so each dup2(sv) amortizes over 16 FFMA2 instead
// of 4 (-96 ALU movs/thread; epilogue live set 114 regs, still no spill).
__global__ __launch_bounds__(256, 2) void fused_graphaug_kernel(
    const float* __restrict__ x,
    float* __restrict__ out)
{
    const int t = threadIdx.x;

    // ---- Pixel-pair indexing (2 horizontally-adjacent pixels per thread) ----
    const int tidg = blockIdx.x * 256 + t;
    const int p0   = tidg * 2;
    const int w0   = p0 & (W512 - 1);            // even column
    const int h    = (p0 >> 9) & (W512 - 1);
    const int b    = p0 >> 18;

    const float* xb    = x + (size_t)b * C16 * HW;
    const int    center = h * W512 + w0;

    // ---- sv = raw sum of 8 rolls per channel (7 packed adds, init = first) ----
    float2 sv[C16];
    {
        constexpr int DY[8] = {-4, -4, -4, -3, -2, 2, 3, 4};
        constexpr int DX[8] = {-4, -1,  2,  4, -3, 3, -2, 4};
        int roff[8], cb[8];
        #pragma unroll
        for (int i = 0; i < 8; i++) {
            roff[i] = ((h - DY[i]) & (W512 - 1)) * W512;
            cb[i]   = (w0 - DX[i]) & (W512 - 1);
        }
        #pragma unroll
        for (int c = 0; c < C16; c++) {
            const float* xp = xb + c * HW;
            // i=0 has even dx -> aligned float2; use it as the initializer
            float2 acc = *reinterpret_cast<const float2*>(xp + roff[0] + cb[0]);
            #pragma unroll
            for (int i = 1; i < 8; i++) {
                float2 v;
                if ((DX[i] & 1) == 0) {
                    // even dx: cb even <= 510 -> aligned contiguous float2
                    v = *reinterpret_cast<const float2*>(xp + roff[i] + cb[i]);
                } else {
                    v.x = __ldg(xp + roff[i] + cb[i]);
                    v.y = __ldg(xp + roff[i] + ((cb[i] + 1) & (W512 - 1)));
                }
                acc = fadd2(acc, v);
            }
            sv[c] = acc;                          // raw sum; 0.125 is in W2'/MW'
        }
    }

    // ---- gate accumulators: gacc[gp][px] packs outputs (2gp, 2gp+1) ----
    float2 gacc[8][2];
    #pragma unroll
    for (int gp = 0; gp < 8; gp++) {
        float2 gb = ldc2(OFF_GB + 2 * gp);
        gacc[gp][0] = gb; gacc[gp][1] = gb;
    }

    // ---- hidden in 2 chunks of 16 units (8 j-pairs each) ----
    #pragma unroll
    for (int jt = 0; jt < 2; jt++) {
        const int j0 = jt * 16;
        float2 hreg[8][2];                       // pairs (j0+2l, j0+2l+1) x 2 px
        #pragma unroll
        for (int jl = 0; jl < 8; jl++) {
            float2 bv = ldc2(OFF_B1 + j0 + 2 * jl);
            hreg[jl][0] = bv; hreg[jl][1] = bv;
        }
        // W1 @ x (const port; x center loaded once per chunk, L1-resident)
        #pragma unroll
        for (int c = 0; c < C16; c++) {
            float2 xc = *reinterpret_cast<const float2*>(xb + c * HW + center);
            float2 xd0 = dup2(xc.x), xd1 = dup2(xc.y);
            #pragma unroll
            for (int q = 0; q < 4; q++) {        // 4 ldc4 cover 16 units
                float4 wq = ldc4(OFF_W1 + c * GH32 + j0 + 4 * q);
                hreg[2*q][0]   = ffma2(make_float2(wq.x, wq.y), xd0, hreg[2*q][0]);
                hreg[2*q][1]   = ffma2(make_float2(wq.x, wq.y), xd1, hreg[2*q][1]);
                hreg[2*q+1][0] = ffma2(make_float2(wq.z, wq.w), xd0, hreg[2*q+1][0]);
                hreg[2*q+1][1] = ffma2(make_float2(wq.z, wq.w), xd1, hreg[2*q+1][1]);
            }
        }
        // W2' @ sv (const port; sv in registers)
        #pragma unroll
        for (int c = 0; c < C16; c++) {
            float2 sd0 = dup2(sv[c].x), sd1 = dup2(sv[c].y);
            #pragma unroll
            for (int q = 0; q < 4; q++) {
                float4 wq = ldc4(OFF_W2 + c * GH32 + j0 + 4 * q);
                hreg[2*q][0]   = ffma2(make_float2(wq.x, wq.y), sd0, hreg[2*q][0]);
                hreg[2*q][1]   = ffma2(make_float2(wq.x, wq.y), sd1, hreg[2*q][1]);
                hreg[2*q+1][0] = ffma2(make_float2(wq.z, wq.w), sd0, hreg[2*q+1][0]);
                hreg[2*q+1][1] = ffma2(make_float2(wq.z, wq.w), sd1, hreg[2*q+1][1]);
            }
        }
        // relu
        #pragma unroll
        for (int jl = 0; jl < 8; jl++) {
            hreg[jl][0].x = fmaxf(hreg[jl][0].x, 0.f);
            hreg[jl][0].y = fmaxf(hreg[jl][0].y, 0.f);
            hreg[jl][1].x = fmaxf(hreg[jl][1].x, 0.f);
            hreg[jl][1].y = fmaxf(hreg[jl][1].y, 0.f);
        }
        // gate accumulation (const port)
        #pragma unroll
        for (int jl = 0; jl < 8; jl++) {
            const int jg = j0 + 2 * jl;
            float2 ha0 = dup2(hreg[jl][0].x), hb0 = dup2(hreg[jl][0].y);
            float2 ha1 = dup2(hreg[jl][1].x), hb1 = dup2(hreg[jl][1].y);
            #pragma unroll
            for (int gp = 0; gp < 8; gp++) {
                float4 wq = ldc4(OFF_G2 + gp * 64 + jg * 2);
                gacc[gp][0] = ffma2(make_float2(wq.x, wq.y), ha0, gacc[gp][0]);
                gacc[gp][0] = ffma2(make_float2(wq.z, wq.w), hb0, gacc[gp][0]);
                gacc[gp][1] = ffma2(make_float2(wq.x, wq.y), ha1, gacc[gp][1]);
                gacc[gp][1] = ffma2(make_float2(wq.z, wq.w), hb1, gacc[gp][1]);
            }
        }
    }

    // ---- agg = MW' @ sv + mb : c-OUTER, all 16 agg accumulators live ----
    // agg[q][px] packs output channels (2q, 2q+1); dup2(sv) amortizes over
    // 16 FFMA2 per c instead of 4 (the R15 dp-outer form).
    float2 agg[8][2];
    #pragma unroll
    for (int q = 0; q < 8; q++) {
        float2 mv = ldc2(OFF_MB + 2 * q);
        agg[q][0] = mv; agg[q][1] = mv;
    }
    #pragma unroll
    for (int c = 0; c < C16; c++) {
        float2 sd0 = dup2(sv[c].x), sd1 = dup2(sv[c].y);
        #pragma unroll
        for (int q = 0; q < 4; q++) {            // 4 ldc4 cover all 16 d
            float4 wq = ldc4(OFF_MW + c * C16 + 4 * q);
            agg[2*q][0]   = ffma2(make_float2(wq.x, wq.y), sd0, agg[2*q][0]);
            agg[2*q][1]   = ffma2(make_float2(wq.x, wq.y), sd1, agg[2*q][1]);
            agg[2*q+1][0] = ffma2(make_float2(wq.z, wq.w), sd0, agg[2*q+1][0]);
            agg[2*q+1][1] = ffma2(make_float2(wq.z, wq.w), sd1, agg[2*q+1][1]);
        }
    }

    // ---- epilogue: out = agg * sigmoid(gacc) ----
    float* ob = out + (size_t)b * C16 * HW + center;
    #pragma unroll
    for (int q = 0; q < 8; q++) {
        const int d0 = 2 * q;
        float g00 = 1.f / (1.f + __expf(-gacc[q][0].x));  // d0   @ px0
        float g01 = 1.f / (1.f + __expf(-gacc[q][1].x));  // d0   @ px1
        float g10 = 1.f / (1.f + __expf(-gacc[q][0].y));  // d0+1 @ px0
        float g11 = 1.f / (1.f + __expf(-gacc[q][1].y));  // d0+1 @ px1
        *reinterpret_cast<float2*>(ob + (size_t)d0 * HW) =
            make_float2(agg[q][0].x * g00, agg[q][1].x * g01);
        *reinterpret_cast<float2*>(ob + (size_t)(d0 + 1) * HW) =
            make_float2(agg[q][0].y * g10, agg[q][1].y * g11);
    }
}

extern "C" void kernel_launch(void* const* d_in, const int* in_sizes, int n_in,
                              void* d_out, int out_size) {
    // metadata order: x, qw, qb, kw, kb, mw, mb, scaling, g1w, g1b, g2w, g2b
    const float* x   = (const float*)d_in[0];
    const float* mw  = (const float*)d_in[5];
    const float* mb  = (const float*)d_in[6];
    const float* g1w = (const float*)d_in[8];
    const float* g1b = (const float*)d_in[9];
    const float* g2w = (const float*)d_in[10];
    const float* g2b = (const float*)d_in[11];
    float* out = (float*)d_out;

    prep_weights<<<1, 256>>>(mw, mb, g1w, g1b, g2w, g2b);

    void* wsrc = nullptr;
    cudaGetSymbolAddress(&wsrc, g_wbuf);
    cudaMemcpyToSymbolAsync(cwts, wsrc, NWC * sizeof(float), 0,
                            cudaMemcpyDeviceToDevice, 0);

    // 1,048,576 px -> 524,288 horizontal pairs -> 2048 blocks x 256 threads
    fused_graphaug_kernel<<<2048, 256>>>(x, out);
}